// round 2
// baseline (speedup 1.0000x reference)
#include <cuda_runtime.h>
#include <math.h>

#define T_TREES 128
#define B_BATCH 1024
#define D_FEAT  784
#define K_TOP   200
#define D4      (D_FEAT / 4)   // 196

#define BT 8   // batch rows per tile
#define TT 4   // tree rows per tile

#define MAX_TIES 64

// Scratch for the selected attention matrix [T, D], float4-aligned.
__device__ float4 g_attn4[T_TREES * D4];

// ---------------------------------------------------------------------------
// Kernel 1: per-tree top-K selection on sigmoid(mask) with jax.lax.top_k tie
// semantics (equal values -> lower index wins). One block per tree.
//
// sigmoid(m) > 0 always, so the raw float bits of s are order-isomorphic as
// uints. Binary search finds the K-th largest key 'lo'; elements with
// key > lo are always kept; among key == lo ties, the 'need' smallest
// indices are kept (need = K - count_gt).
// ---------------------------------------------------------------------------
__global__ __launch_bounds__(256) void attn_select_kernel(
    const float* __restrict__ mask, float* __restrict__ attn_out_tail)
{
    const int t   = blockIdx.x;
    const int tid = threadIdx.x;
    const float* row = mask + t * D_FEAT;

    // Each thread owns up to 4 strided elements (784 = 3*256 + 16).
    unsigned keys[4];
    float    svals[4];
    int n = 0;
    for (int d = tid; d < D_FEAT; d += 256) {
        float m = row[d];
        float s = 1.0f / (1.0f + expf(-m));
        svals[n] = s;
        keys[n]  = __float_as_uint(s);   // s > 0 -> bits are monotone key
        n++;
    }

    __shared__ int wsum[8];
    __shared__ int s_count;
    __shared__ int s_tie_count;
    __shared__ int s_tie_idx[MAX_TIES];

    // Block-wide count of (key >= thresh).
    auto block_count_ge = [&](unsigned thresh) -> int {
        int c = 0;
        #pragma unroll
        for (int i = 0; i < 4; i++)
            if (i < n) c += (keys[i] >= thresh);
        #pragma unroll
        for (int o = 16; o > 0; o >>= 1)
            c += __shfl_down_sync(0xFFFFFFFFu, c, o);
        if ((tid & 31) == 0) wsum[tid >> 5] = c;
        __syncthreads();
        if (tid == 0) {
            int s = 0;
            #pragma unroll
            for (int w = 0; w < 8; w++) s += wsum[w];
            s_count = s;
        }
        __syncthreads();
        int r = s_count;
        __syncthreads();   // protect wsum/s_count for next call
        return r;
    };

    // Find max lo with count(key >= lo) >= K  (== key of the K-th largest).
    unsigned lo = 0u, hi = 0x3F800000u;  // s in (0, 1) -> key < bits(1.0f)
    while (lo < hi) {
        unsigned mid = lo + ((hi - lo + 1u) >> 1);
        if (block_count_ge(mid) >= K_TOP) lo = mid; else hi = mid - 1u;
    }

    // Strictly-greater count -> how many tie slots we still need.
    int count_gt = block_count_ge(lo + 1u);
    int need = K_TOP - count_gt;

    // Collect tie indices (key == lo).
    if (tid == 0) s_tie_count = 0;
    __syncthreads();
    {
        int i = 0;
        for (int d = tid; d < D_FEAT; d += 256) {
            if (keys[i] == lo) {
                int slot = atomicAdd(&s_tie_count, 1);
                if (slot < MAX_TIES) s_tie_idx[slot] = d;
            }
            i++;
        }
    }
    __syncthreads();
    int n_ties = min(s_tie_count, MAX_TIES);

    // Write: keep key > lo, plus ties whose index-rank among ties < need.
    float* g_attn = (float*)g_attn4;
    {
        int i = 0;
        for (int d = tid; d < D_FEAT; d += 256) {
            bool keep = (keys[i] > lo);
            if (keys[i] == lo) {
                int rank = 0;
                for (int j = 0; j < n_ties; j++)
                    rank += (s_tie_idx[j] < d);
                keep = (rank < need);
            }
            float outv = keep ? svals[i] : 0.0f;
            g_attn[t * D_FEAT + d]        = outv;
            attn_out_tail[t * D_FEAT + d] = outv;
            i++;
        }
    }
}

// ---------------------------------------------------------------------------
// Kernel 2: out[b,t,d] = x[b,d] * attn[t,d], tiled (BT x TT) through shared
// memory so L2 read traffic is ~0.375x of the 411 MB write stream (keeps the
// kernel DRAM-store-bound instead of LTS-bound). x float4 held in a register
// across the TT inner iterations.
// ---------------------------------------------------------------------------
__global__ __launch_bounds__(256) void bcast_mul_kernel(
    const float* __restrict__ x, float* __restrict__ out)
{
    __shared__ float4 sx[BT * D4];  // 1568 float4 = 25088 B
    __shared__ float4 sa[TT * D4];  //  784 float4 = 12544 B

    const int tb  = blockIdx.x;
    const int t0  = (tb & 31) * TT;        // 128/TT = 32 t-tiles
    const int b0  = (tb >> 5) * BT;        // 1024/BT = 128 b-tiles
    const int tid = threadIdx.x;

    const float4* x4 = (const float4*)x;
    for (int j = tid; j < BT * D4; j += 256)
        sx[j] = x4[(b0 + j / D4) * D4 + (j % D4)];
    for (int j = tid; j < TT * D4; j += 256)
        sa[j] = g_attn4[(t0 + j / D4) * D4 + (j % D4)];
    __syncthreads();

    float4* o4 = (float4*)out;
    for (int j = tid; j < BT * D4; j += 256) {
        const int bl = j / D4;
        const int d4 = j % D4;
        const float4 xv = sx[j];
        const int base = ((b0 + bl) * T_TREES + t0) * D4 + d4;  // < 2^31
        #pragma unroll
        for (int tl = 0; tl < TT; tl++) {
            float4 av = sa[tl * D4 + d4];
            float4 r;
            r.x = xv.x * av.x;
            r.y = xv.y * av.y;
            r.z = xv.z * av.z;
            r.w = xv.w * av.w;
            o4[base + tl * D4] = r;
        }
    }
}

extern "C" void kernel_launch(void* const* d_in, const int* in_sizes, int n_in,
                              void* d_out, int out_size)
{
    const float* x    = (const float*)d_in[0];
    const float* mask = (const float*)d_in[1];
    // Defensive: identify by element count (x: 802816, mask: 100352).
    if (n_in >= 2 && in_sizes[0] == T_TREES * D_FEAT) {
        x    = (const float*)d_in[1];
        mask = (const float*)d_in[0];
    }

    float* out = (float*)d_out;
    float* attn_tail = out + (size_t)B_BATCH * T_TREES * D_FEAT;

    attn_select_kernel<<<T_TREES, 256>>>(mask, attn_tail);
    bcast_mul_kernel<<<(B_BATCH / BT) * (T_TREES / TT), 256>>>(x, out);
}

// round 3
// speedup vs baseline: 1.0789x; 1.0789x over previous
#include <cuda_runtime.h>
#include <math.h>

#define T_TREES 128
#define B_BATCH 1024
#define D_FEAT  784
#define K_TOP   200
#define D4      (D_FEAT / 4)   // 196

#define BT 8   // batch rows per tile
#define TT 4   // tree rows per tile

#define NSLOT 25   // ceil(784/32)

// Scratch for the selected attention matrix [T, D], float4-aligned.
__device__ float4 g_attn4[T_TREES * D4];

// ---------------------------------------------------------------------------
// Kernel 1: per-tree top-K selection, ONE WARP PER TREE.
// Warp-only collectives (REDUX.SUM via __reduce_add_sync + ballots): no
// shared memory, no block barriers. Exact K-th key by 32-step binary search
// on the uint bits of sigmoid(m) (s>0 so bits are order-isomorphic); ties at
// the K-th value broken by lowest index first (jax.lax.top_k semantics).
// ---------------------------------------------------------------------------
__global__ __launch_bounds__(32) void attn_select_kernel(
    const float* __restrict__ mask, float* __restrict__ attn_out_tail)
{
    const int t    = blockIdx.x;
    const int lane = threadIdx.x;
    const float* row = mask + t * D_FEAT;

    // Element i of this lane is d = i*32 + lane (valid while d < 784).
    unsigned keys[NSLOT];
    float    svals[NSLOT];
    #pragma unroll
    for (int i = 0; i < NSLOT; i++) {
        int d = i * 32 + lane;
        if (d < D_FEAT) {
            float m = row[d];
            float s = 1.0f / (1.0f + expf(-m));
            svals[i] = s;
            keys[i]  = __float_as_uint(s);  // s in (0,1) -> monotone key, >0
        } else {
            svals[i] = 0.0f;
            keys[i]  = 0u;                  // never >= any searched threshold
        }
    }

    // Binary search for the K-th largest key: max lo with count(>= lo) >= K.
    unsigned lo = 0u, hi = 0x3F800000u;     // s < 1.0f
    while (lo < hi) {
        unsigned mid = lo + ((hi - lo + 1u) >> 1);   // mid >= 1
        int c = 0;
        #pragma unroll
        for (int i = 0; i < NSLOT; i++) c += (keys[i] >= mid);
        c = __reduce_add_sync(0xFFFFFFFFu, c);
        if (c >= K_TOP) lo = mid; else hi = mid - 1u;
    }

    // Strictly-greater count -> tie slots still needed.
    int cg = 0;
    #pragma unroll
    for (int i = 0; i < NSLOT; i++) cg += (keys[i] > lo);
    cg = __reduce_add_sync(0xFFFFFFFFu, cg);
    const int need = K_TOP - cg;

    // Write with tie ranking: among key == lo, lowest global index d wins.
    float* g_attn = (float*)g_attn4;
    const unsigned below = (1u << lane) - 1u;
    int running = 0;  // ties in slots < i (uniform across warp)
    #pragma unroll
    for (int i = 0; i < NSLOT; i++) {
        int d = i * 32 + lane;
        bool tie = (keys[i] == lo) && (d < D_FEAT);
        unsigned bm = __ballot_sync(0xFFFFFFFFu, tie);
        int rank = running + __popc(bm & below);
        bool keep = (keys[i] > lo) || (tie && rank < need);
        running += __popc(bm);
        if (d < D_FEAT) {
            float outv = keep ? svals[i] : 0.0f;
            g_attn[t * D_FEAT + d]        = outv;
            attn_out_tail[t * D_FEAT + d] = outv;
        }
    }
}

// ---------------------------------------------------------------------------
// Kernel 2: out[b,t,d] = x[b,d] * attn[t,d], tiled (BT x TT) through shared
// memory so L2 read traffic stays well under the LTS cap and DRAM sees a
// pure 411 MB write stream. x float4 held in a register across the TT inner
// iterations; streaming stores (evict-first) since output is never re-read.
// ---------------------------------------------------------------------------
__global__ __launch_bounds__(256) void bcast_mul_kernel(
    const float* __restrict__ x, float* __restrict__ out)
{
    __shared__ float4 sx[BT * D4];  // 25088 B
    __shared__ float4 sa[TT * D4];  // 12544 B

    const int tb  = blockIdx.x;
    const int t0  = (tb & 31) * TT;        // 128/TT = 32 t-tiles
    const int b0  = (tb >> 5) * BT;        // 1024/BT = 128 b-tiles
    const int tid = threadIdx.x;

    const float4* x4 = (const float4*)x;
    for (int j = tid; j < BT * D4; j += 256)
        sx[j] = x4[(b0 + j / D4) * D4 + (j % D4)];
    for (int j = tid; j < TT * D4; j += 256)
        sa[j] = g_attn4[(t0 + j / D4) * D4 + (j % D4)];
    __syncthreads();

    float4* o4 = (float4*)out;
    for (int j = tid; j < BT * D4; j += 256) {
        const int bl = j / D4;
        const int d4 = j % D4;
        const float4 xv = sx[j];
        const int base = ((b0 + bl) * T_TREES + t0) * D4 + d4;
        #pragma unroll
        for (int tl = 0; tl < TT; tl++) {
            float4 av = sa[tl * D4 + d4];
            float4 r;
            r.x = xv.x * av.x;
            r.y = xv.y * av.y;
            r.z = xv.z * av.z;
            r.w = xv.w * av.w;
            __stcs(&o4[base + tl * D4], r);
        }
    }
}

extern "C" void kernel_launch(void* const* d_in, const int* in_sizes, int n_in,
                              void* d_out, int out_size)
{
    const float* x    = (const float*)d_in[0];
    const float* mask = (const float*)d_in[1];
    // Defensive: identify by element count (x: 802816, mask: 100352).
    if (n_in >= 2 && in_sizes[0] == T_TREES * D_FEAT) {
        x    = (const float*)d_in[1];
        mask = (const float*)d_in[0];
    }

    float* out = (float*)d_out;
    float* attn_tail = out + (size_t)B_BATCH * T_TREES * D_FEAT;

    attn_select_kernel<<<T_TREES, 32>>>(mask, attn_tail);
    bcast_mul_kernel<<<(B_BATCH / BT) * (T_TREES / TT), 256>>>(x, out);
}

// round 4
// speedup vs baseline: 1.1339x; 1.0510x over previous
#include <cuda_runtime.h>
#include <math.h>

#define T_TREES 128
#define B_BATCH 1024
#define D_FEAT  784
#define K_TOP   200
#define D4      (D_FEAT / 4)   // 196

#define BT 8   // batch rows per tile
#define TT 4   // tree rows per tile
#define NJ 7   // ceil(BT*D4 / 256) = ceil(1568/256)

#define NSLOT 25   // ceil(784/32)

// Scratch for the selected attention matrix [T, D], float4-aligned.
__device__ float4 g_attn4[T_TREES * D4];

// ---------------------------------------------------------------------------
// Kernel 1: per-tree top-K selection, ONE WARP PER TREE.
// Warp-only collectives (REDUX.SUM + ballots). Exact K-th key via binary
// search on the uint bits of sigmoid(m); ties at the K-th value broken by
// lowest index first (jax.lax.top_k semantics). Fires the PDL trigger as
// soon as g_attn is written so the broadcast kernel can proceed.
// ---------------------------------------------------------------------------
__global__ __launch_bounds__(32) void attn_select_kernel(
    const float* __restrict__ mask, float* __restrict__ attn_out_tail)
{
    const int t    = blockIdx.x;
    const int lane = threadIdx.x;
    const float* row = mask + t * D_FEAT;

    unsigned keys[NSLOT];
    float    svals[NSLOT];
    #pragma unroll
    for (int i = 0; i < NSLOT; i++) {
        int d = i * 32 + lane;
        if (d < D_FEAT) {
            float m = row[d];
            float s = 1.0f / (1.0f + expf(-m));
            svals[i] = s;
            keys[i]  = __float_as_uint(s);  // s in (0,1) -> monotone key, >0
        } else {
            svals[i] = 0.0f;
            keys[i]  = 0u;
        }
    }

    // K-th largest key: max lo with count(key >= lo) >= K.
    // mask ~ U[-1,1) -> s in (sig(-1), sig(1)) = (0.2689, 0.7311);
    // bounds with slack: [0.125, 0.75).
    unsigned lo = 0x3E000000u, hi = 0x3F400000u;
    while (lo < hi) {
        unsigned mid = lo + ((hi - lo + 1u) >> 1);
        int c = 0;
        #pragma unroll
        for (int i = 0; i < NSLOT; i++) c += (keys[i] >= mid);
        c = __reduce_add_sync(0xFFFFFFFFu, c);
        if (c >= K_TOP) lo = mid; else hi = mid - 1u;
    }

    int cg = 0;
    #pragma unroll
    for (int i = 0; i < NSLOT; i++) cg += (keys[i] > lo);
    cg = __reduce_add_sync(0xFFFFFFFFu, cg);
    const int need = K_TOP - cg;

    // Compute keep flags + write g_attn (consumed by bcast kernel).
    float* g_attn = (float*)g_attn4;
    float outv[NSLOT];
    const unsigned below = (1u << lane) - 1u;
    int running = 0;
    #pragma unroll
    for (int i = 0; i < NSLOT; i++) {
        int d = i * 32 + lane;
        bool tie = (keys[i] == lo) && (d < D_FEAT);
        unsigned bm = __ballot_sync(0xFFFFFFFFu, tie);
        int rank = running + __popc(bm & below);
        bool keep = (keys[i] > lo) || (tie && rank < need);
        running += __popc(bm);
        outv[i] = keep ? svals[i] : 0.0f;
        if (d < D_FEAT) g_attn[t * D_FEAT + d] = outv[i];
    }

    __threadfence();
#if defined(__CUDA_ARCH__) && __CUDA_ARCH__ >= 900
    cudaTriggerProgrammaticLaunchCompletion();
#endif

    // Tail copy of attention (output 1) — off the critical path.
    #pragma unroll
    for (int i = 0; i < NSLOT; i++) {
        int d = i * 32 + lane;
        if (d < D_FEAT) attn_out_tail[t * D_FEAT + d] = outv[i];
    }
}

// ---------------------------------------------------------------------------
// Kernel 2: out[b,t,d] = x[b,d] * attn[t,d].
// x float4s prefetched into registers BEFORE the grid-dependency sync (they
// don't depend on kernel 1), attn tile staged in smem (8x reuse across the
// BT batch rows). Streaming stores: the 411 MB output is never re-read.
// ---------------------------------------------------------------------------
__global__ __launch_bounds__(256) void bcast_mul_kernel(
    const float4* __restrict__ x4, float4* __restrict__ o4)
{
    __shared__ float4 sa[TT * D4];  // 12544 B

    const int tb  = blockIdx.x;
    const int t0  = (tb & 31) * TT;        // 128/TT = 32 t-tiles
    const int b0  = (tb >> 5) * BT;        // 1024/BT = 128 b-tiles
    const int tid = threadIdx.x;

    // Prefetch this thread's x elements (overlaps with kernel 1 under PDL).
    float4 xv[NJ];
    #pragma unroll
    for (int k = 0; k < NJ; k++) {
        int j = tid + k * 256;
        if (j < BT * D4) xv[k] = __ldg(&x4[b0 * D4 + j]);  // (b0+bl)*D4+d4
    }

#if defined(__CUDA_ARCH__) && __CUDA_ARCH__ >= 900
    cudaGridDependencySynchronize();
#endif

    for (int j = tid; j < TT * D4; j += 256)
        sa[j] = g_attn4[t0 * D4 + j];       // rows t0..t0+3 are contiguous
    __syncthreads();

    #pragma unroll
    for (int k = 0; k < NJ; k++) {
        int j = tid + k * 256;
        if (j >= BT * D4) break;
        const int bl = j / D4;
        const int d4 = j - bl * D4;
        const float4 v = xv[k];
        const int base = ((b0 + bl) * T_TREES + t0) * D4 + d4;
        #pragma unroll
        for (int tl = 0; tl < TT; tl++) {
            float4 av = sa[tl * D4 + d4];
            float4 r;
            r.x = v.x * av.x;
            r.y = v.y * av.y;
            r.z = v.z * av.z;
            r.w = v.w * av.w;
            __stcs(&o4[base + tl * D4], r);
        }
    }
}

extern "C" void kernel_launch(void* const* d_in, const int* in_sizes, int n_in,
                              void* d_out, int out_size)
{
    const float* x    = (const float*)d_in[0];
    const float* mask = (const float*)d_in[1];
    if (n_in >= 2 && in_sizes[0] == T_TREES * D_FEAT) {
        x    = (const float*)d_in[1];
        mask = (const float*)d_in[0];
    }

    float* out = (float*)d_out;
    float* attn_tail = out + (size_t)B_BATCH * T_TREES * D_FEAT;

    attn_select_kernel<<<T_TREES, 32>>>(mask, attn_tail);

    // Broadcast kernel with programmatic dependent launch: starts while the
    // selection kernel runs, blocks at cudaGridDependencySynchronize().
    {
        cudaLaunchConfig_t cfg = {};
        cfg.gridDim  = dim3((B_BATCH / BT) * (T_TREES / TT));
        cfg.blockDim = dim3(256);
        cfg.dynamicSmemBytes = 0;
        cfg.stream = 0;
        cudaLaunchAttribute attr[1];
        attr[0].id = cudaLaunchAttributeProgrammaticStreamSerialization;
        attr[0].val.programmaticStreamSerializationAllowed = 1;
        cfg.attrs = attr;
        cfg.numAttrs = 1;
        cudaLaunchKernelEx(&cfg, bcast_mul_kernel,
                           (const float4*)x, (float4*)out);
    }
}